// round 14
// baseline (speedup 1.0000x reference)
#include <cuda_runtime.h>
#include <cstdint>

// SetEmbed: out[b] = (sum_{s<n_b} relu(X[b,s]@W1 + b1)) @ W2 + n_b*b2, then @ W3 + b3.
// Single fused kernel. One CTA per (batch, 128-row tile): cp.async staged X,
// 64x16 GEMM on tensor pipe via mma.sync.m16n8k8.tf32 (cvt.rna pre-round),
// row-masked relu+pool, partial pooled16 -> scratch. Last-finishing CTA per batch
// (threadfence reduction, self-resetting counter) runs the W2/W3 warp epilogue inline.

#define B_      2048
#define S_      512
#define NFT     64
#define K1      16
#define K2      12
#define NOUT    32
#define TSR     128
#define NTILES  (S_ / TSR)          // 4
#define RST     68                  // floats per smem row (pad: conflict-free frags)
#define NTHREADS 128

__device__ float g_scratch[B_ * NTILES * K1];   // [b][tile][k] partial pooled sums
__device__ int   g_cnt[B_];                     // completion counters (self-resetting)

__device__ __forceinline__ uint32_t f2tf32(float x) {
    uint32_t r;
    asm("cvt.rna.tf32.f32 %0, %1;" : "=r"(r) : "f"(x));
    return r;
}
__device__ __forceinline__ uint32_t smem_u32(const void* p) {
    return (uint32_t)__cvta_generic_to_shared(p);
}
__device__ __forceinline__ void mma16n8k8(float c[4], uint32_t a0, uint32_t a1,
                                          uint32_t a2, uint32_t a3,
                                          uint32_t b0, uint32_t b1) {
    asm volatile(
        "mma.sync.aligned.m16n8k8.row.col.f32.tf32.tf32.f32 "
        "{%0,%1,%2,%3}, {%4,%5,%6,%7}, {%8,%9}, {%0,%1,%2,%3};"
        : "+f"(c[0]), "+f"(c[1]), "+f"(c[2]), "+f"(c[3])
        : "r"(a0), "r"(a1), "r"(a2), "r"(a3), "r"(b0), "r"(b1));
}

__global__ __launch_bounds__(NTHREADS, 6) void setembed_fused(
    const float* __restrict__ X, const int* __restrict__ setSizes,
    const float* __restrict__ W1, const float* __restrict__ b1,
    const float* __restrict__ W2, const float* __restrict__ b2,
    const float* __restrict__ W3, const float* __restrict__ b3,
    float* __restrict__ out)
{
    __shared__ __align__(16) float Xs[TSR * RST];    // 34816 B
    __shared__ float red[4][K1];
    __shared__ int   flag_s;

    const int bid  = blockIdx.x;
    const int b    = bid >> 2;
    const int tile = bid & 3;
    const int t    = threadIdx.x;
    const int n    = setSizes[b];
    const int base = tile * TSR;
    const int nact = (n > 0) ? ((n + TSR - 1) >> 7) : 1;  // tiles that participate

    if (tile > 0 && base >= n) return;     // inactive tile (tile 0 always runs)
    const int cnt = max(0, min(TSR, n - base));

    // Stage cnt rows, coalesced float4 cp.async. Tail rows stay garbage in smem;
    // their MMA outputs are masked before pooling (rows independent in the GEMM).
    {
        const float4* Xg = reinterpret_cast<const float4*>(
            X + (size_t)b * S_ * NFT) + (size_t)base * 16;
#pragma unroll
        for (int m = 0; m < 16; m++) {
            int idx = t + m * NTHREADS;    // 0..2047 float4 slots
            int r = idx >> 4, c = idx & 15;
            if (r < cnt) {
                unsigned da = smem_u32(&Xs[r * RST + c * 4]);
                asm volatile("cp.async.cg.shared.global [%0], [%1], 16;"
                             :: "r"(da), "l"(&Xg[r * 16 + c]));
            }
        }
        asm volatile("cp.async.commit_group;");
    }

    const int lane = t & 31, warp = t >> 5;
    const int lr = lane & 3;               // k-in-group / C col-pair id
    const int lg = lane >> 2;              // m-in-group / B n id

    // B fragments (W1^T as tf32), register-resident; LDG overlaps cp.async.
    uint32_t bf[8][2][2];                  // [kt][nt][b0/b1]
#pragma unroll
    for (int kt = 0; kt < 8; kt++)
#pragma unroll
        for (int nt = 0; nt < 2; nt++) {
            bf[kt][nt][0] = f2tf32(W1[(kt * 8 + lr)     * K1 + nt * 8 + lg]);
            bf[kt][nt][1] = f2tf32(W1[(kt * 8 + lr + 4) * K1 + nt * 8 + lg]);
        }
    float b1c[4];
    b1c[0] = b1[2 * lr];     b1c[1] = b1[2 * lr + 1];
    b1c[2] = b1[8 + 2 * lr]; b1c[3] = b1[8 + 2 * lr + 1];

    asm volatile("cp.async.wait_group 0;");
    __syncthreads();

    float accp[4] = {0.f, 0.f, 0.f, 0.f};
#pragma unroll
    for (int i = 0; i < 2; i++) {          // 2 m-tiles per warp
        const int r0b = (2 * warp + i) * 16;
        if (r0b < cnt) {                   // warp-uniform guard
            float c0[4] = {0.f, 0.f, 0.f, 0.f};
            float c1[4] = {0.f, 0.f, 0.f, 0.f};
#pragma unroll
            for (int kt = 0; kt < 8; kt++) {
                const float* xp = &Xs[(r0b + lg) * RST + kt * 8 + lr];
                uint32_t a0 = f2tf32(xp[0]);
                uint32_t a1 = f2tf32(xp[8 * RST]);
                uint32_t a2 = f2tf32(xp[4]);
                uint32_t a3 = f2tf32(xp[8 * RST + 4]);
                mma16n8k8(c0, a0, a1, a2, a3, bf[kt][0][0], bf[kt][0][1]);
                mma16n8k8(c1, a0, a1, a2, a3, bf[kt][1][0], bf[kt][1][1]);
            }
            const int r0 = r0b + lg, r1 = r0 + 8;
            if (r0 < cnt) {                // relu + pool, row-masked
                accp[0] += fmaxf(c0[0] + b1c[0], 0.f);
                accp[1] += fmaxf(c0[1] + b1c[1], 0.f);
                accp[2] += fmaxf(c1[0] + b1c[2], 0.f);
                accp[3] += fmaxf(c1[1] + b1c[3], 0.f);
            }
            if (r1 < cnt) {
                accp[0] += fmaxf(c0[2] + b1c[0], 0.f);
                accp[1] += fmaxf(c0[3] + b1c[1], 0.f);
                accp[2] += fmaxf(c1[2] + b1c[2], 0.f);
                accp[3] += fmaxf(c1[3] + b1c[3], 0.f);
            }
        }
    }

    // Reduce over the 8 row-groups (lanes sharing lr). Deterministic.
#pragma unroll
    for (int j = 0; j < 4; j++) {
        accp[j] += __shfl_xor_sync(0xffffffffu, accp[j], 16);
        accp[j] += __shfl_xor_sync(0xffffffffu, accp[j], 8);
        accp[j] += __shfl_xor_sync(0xffffffffu, accp[j], 4);
    }
    if (lg == 0) {
        red[warp][2 * lr]         = accp[0];
        red[warp][2 * lr + 1]     = accp[1];
        red[warp][8 + 2 * lr]     = accp[2];
        red[warp][8 + 2 * lr + 1] = accp[3];
    }
    __syncthreads();
    if (t < K1) {
        g_scratch[(b * NTILES + tile) * K1 + t] =
            (red[0][t] + red[1][t]) + (red[2][t] + red[3][t]);
        __threadfence();                   // publish partial before counter bump
    }
    __syncthreads();

    if (t == 0) {
        int old = atomicAdd(&g_cnt[b], 1);
        flag_s = (old == nact - 1);
        if (flag_s) g_cnt[b] = 0;          // self-reset for graph replay
    }
    __syncthreads();
    if (!flag_s) return;

    // ---- last finisher for batch b: warp 0 runs the W2/W3 epilogue ----
    if (warp != 0) return;
    __threadfence();                       // acquire: see other tiles' partials
    const int k = lane & 15;
    const int h = lane >> 4;
    const float* sc = &g_scratch[b * NTILES * K1];
    float v = 0.f;
    for (int cc = h; cc < nact; cc += 2) v += sc[cc * K1 + k];  // fixed order
    v += __shfl_xor_sync(0xffffffffu, v, 16);  // lane kk (<16) holds accs[kk]

    const float fn = (float)n;
    float p = (lane < K2) ? fn * b2[lane] : 0.f;   // mask-summed b2 term
#pragma unroll
    for (int kk = 0; kk < K1; kk++) {
        float a = __shfl_sync(0xffffffffu, v, kk);
        if (lane < K2) p += a * W2[kk * K2 + lane];
    }
    float o = b3[lane];
#pragma unroll
    for (int m = 0; m < K2; m++) {
        float pm = __shfl_sync(0xffffffffu, p, m);
        o += pm * W3[m * NOUT + lane];
    }
    out[(size_t)b * NOUT + lane] = o;
}

extern "C" void kernel_launch(void* const* d_in, const int* in_sizes, int n_in,
                              void* d_out, int out_size)
{
    const float* X  = (const float*)d_in[0];
    const int*   ss = (const int*)  d_in[1];
    const float* W1 = (const float*)d_in[2];
    const float* b1 = (const float*)d_in[3];
    const float* W2 = (const float*)d_in[4];
    const float* b2 = (const float*)d_in[5];
    const float* W3 = (const float*)d_in[6];
    const float* b3 = (const float*)d_in[7];
    float* o = (float*)d_out;
    setembed_fused<<<B_ * NTILES, NTHREADS>>>(X, ss, W1, b1, W2, b2, W3, b3, o);
}

// round 16
// speedup vs baseline: 1.1702x; 1.1702x over previous
#include <cuda_runtime.h>
#include <cstdint>

// SetEmbed: out[b] = (sum_{s<n_b} relu(X[b,s]@W1 + b1)) @ W2 + n_b*b2, then @ W3 + b3.
// Linear-fold refactor: out[b] = pooled16 @ (W2@W3) + n_b*(b2@W3) + b3.
//  K1: init kernel writes the constant term  n_b*(b2@W3) + b3  (tiny, grid 256).
//  K2: one CTA per (batch, 128-row tile): cp.async staged X, 64x16 GEMM via
//      mma.sync.m16n8k8.tf32 (cvt.rna pre-round), row-masked relu+pool,
//      partial16 @ W23 (W23 built in smem during the cp.async shadow),
//      fire-and-forget red.global.add.f32 into out[b]. No fences, no counters.

#define B_      2048
#define S_      512
#define NFT     64
#define K1      16
#define K2      12
#define NOUT    32
#define TSR     128
#define NTILES  (S_ / TSR)          // 4
#define RST     68                  // floats per smem row (pad: conflict-free frags)
#define NTHREADS 128

__device__ __forceinline__ uint32_t f2tf32(float x) {
    uint32_t r;
    asm("cvt.rna.tf32.f32 %0, %1;" : "=r"(r) : "f"(x));
    return r;
}
__device__ __forceinline__ uint32_t smem_u32(const void* p) {
    return (uint32_t)__cvta_generic_to_shared(p);
}
__device__ __forceinline__ void mma16n8k8(float c[4], uint32_t a0, uint32_t a1,
                                          uint32_t a2, uint32_t a3,
                                          uint32_t b0, uint32_t b1) {
    asm volatile(
        "mma.sync.aligned.m16n8k8.row.col.f32.tf32.tf32.f32 "
        "{%0,%1,%2,%3}, {%4,%5,%6,%7}, {%8,%9}, {%0,%1,%2,%3};"
        : "+f"(c[0]), "+f"(c[1]), "+f"(c[2]), "+f"(c[3])
        : "r"(a0), "r"(a1), "r"(a2), "r"(a3), "r"(b0), "r"(b1));
}
__device__ __forceinline__ void redg_add(float* p, float v) {
    asm volatile("red.global.add.f32 [%0], %1;" :: "l"(p), "f"(v) : "memory");
}

// K1: out[b][o] = n_b * (b2@W3)[o] + b3[o]
__global__ __launch_bounds__(256) void setembed_init(
    const int* __restrict__ setSizes,
    const float* __restrict__ b2, const float* __restrict__ W3,
    const float* __restrict__ b3, float* __restrict__ out)
{
    __shared__ float c32[NOUT];      // (b2@W3)[o] + ... computed once per block
    const int t = threadIdx.x;
    if (t < NOUT) {
        float s = 0.f;
#pragma unroll
        for (int m = 0; m < K2; m++) s += b2[m] * W3[m * NOUT + t];
        c32[t] = s;
    }
    __syncthreads();
    const int idx = blockIdx.x * 256 + t;   // 0 .. B_*NOUT-1
    const int b = idx >> 5, o = idx & 31;
    out[idx] = (float)setSizes[b] * c32[o] + b3[o];
}

__global__ __launch_bounds__(NTHREADS, 6) void setembed_main(
    const float* __restrict__ X, const int* __restrict__ setSizes,
    const float* __restrict__ W1, const float* __restrict__ b1,
    const float* __restrict__ W2, const float* __restrict__ W3,
    float* __restrict__ out)
{
    __shared__ __align__(16) float Xs[TSR * RST];    // 34816 B
    __shared__ float W23s[K1 * NOUT];                // 2048 B
    __shared__ float red[4][K1];
    __shared__ float ps[K1];

    const int bid  = blockIdx.x;
    const int b    = bid >> 2;
    const int tile = bid & 3;
    const int t    = threadIdx.x;
    const int n    = setSizes[b];
    const int base = tile * TSR;

    if (base >= n) return;            // inactive tile contributes exactly zero
    const int cnt = min(TSR, n - base);

    // Stage cnt rows, coalesced float4 cp.async. Tail rows stay garbage in smem;
    // their MMA outputs are masked before pooling (rows independent in the GEMM).
    {
        const float4* Xg = reinterpret_cast<const float4*>(
            X + (size_t)b * S_ * NFT) + (size_t)base * 16;
#pragma unroll
        for (int m = 0; m < 16; m++) {
            int idx = t + m * NTHREADS;       // 0..2047 float4 slots
            int r = idx >> 4, c = idx & 15;
            if (r < cnt) {
                unsigned da = smem_u32(&Xs[r * RST + c * 4]);
                asm volatile("cp.async.cg.shared.global [%0], [%1], 16;"
                             :: "r"(da), "l"(&Xg[r * 16 + c]));
            }
        }
        asm volatile("cp.async.commit_group;");
    }

    const int lane = t & 31, warp = t >> 5;
    const int lr = lane & 3;          // k-in-group / C col-pair id
    const int lg = lane >> 2;         // m-in-group / B n id

    // B fragments (W1^T as tf32), register-resident; overlaps cp.async.
    uint32_t bf[8][2][2];             // [kt][nt][b0/b1]
#pragma unroll
    for (int kt = 0; kt < 8; kt++)
#pragma unroll
        for (int nt = 0; nt < 2; nt++) {
            bf[kt][nt][0] = f2tf32(W1[(kt * 8 + lr)     * K1 + nt * 8 + lg]);
            bf[kt][nt][1] = f2tf32(W1[(kt * 8 + lr + 4) * K1 + nt * 8 + lg]);
        }
    float b1c[4];
    b1c[0] = b1[2 * lr];     b1c[1] = b1[2 * lr + 1];
    b1c[2] = b1[8 + 2 * lr]; b1c[3] = b1[8 + 2 * lr + 1];

    // W23 = W2@W3 into smem (L2-hot operands), also in the cp.async shadow.
#pragma unroll
    for (int e = 0; e < 4; e++) {
        int idx = t * 4 + e;          // 0..511
        int k = idx >> 5, o = idx & 31;
        float s = 0.f;
#pragma unroll
        for (int m = 0; m < K2; m++) s += W2[k * K2 + m] * W3[m * NOUT + o];
        W23s[idx] = s;
    }

    asm volatile("cp.async.wait_group 0;");
    __syncthreads();

    float accp[4] = {0.f, 0.f, 0.f, 0.f};
#pragma unroll
    for (int i = 0; i < 2; i++) {     // 2 m-tiles per warp
        const int r0b = (2 * warp + i) * 16;
        if (r0b < cnt) {              // warp-uniform guard
            float c0[4] = {0.f, 0.f, 0.f, 0.f};
            float c1[4] = {0.f, 0.f, 0.f, 0.f};
#pragma unroll
            for (int kt = 0; kt < 8; kt++) {
                const float* xp = &Xs[(r0b + lg) * RST + kt * 8 + lr];
                uint32_t a0 = f2tf32(xp[0]);
                uint32_t a1 = f2tf32(xp[8 * RST]);
                uint32_t a2 = f2tf32(xp[4]);
                uint32_t a3 = f2tf32(xp[8 * RST + 4]);
                mma16n8k8(c0, a0, a1, a2, a3, bf[kt][0][0], bf[kt][0][1]);
                mma16n8k8(c1, a0, a1, a2, a3, bf[kt][1][0], bf[kt][1][1]);
            }
            const int r0 = r0b + lg, r1 = r0 + 8;
            if (r0 < cnt) {           // relu + pool, row-masked
                accp[0] += fmaxf(c0[0] + b1c[0], 0.f);
                accp[1] += fmaxf(c0[1] + b1c[1], 0.f);
                accp[2] += fmaxf(c1[0] + b1c[2], 0.f);
                accp[3] += fmaxf(c1[1] + b1c[3], 0.f);
            }
            if (r1 < cnt) {
                accp[0] += fmaxf(c0[2] + b1c[0], 0.f);
                accp[1] += fmaxf(c0[3] + b1c[1], 0.f);
                accp[2] += fmaxf(c1[2] + b1c[2], 0.f);
                accp[3] += fmaxf(c1[3] + b1c[3], 0.f);
            }
        }
    }

    // Reduce over the 8 row-groups (lanes sharing lr). Deterministic per CTA.
#pragma unroll
    for (int j = 0; j < 4; j++) {
        accp[j] += __shfl_xor_sync(0xffffffffu, accp[j], 16);
        accp[j] += __shfl_xor_sync(0xffffffffu, accp[j], 8);
        accp[j] += __shfl_xor_sync(0xffffffffu, accp[j], 4);
    }
    if (lg == 0) {
        red[warp][2 * lr]         = accp[0];
        red[warp][2 * lr + 1]     = accp[1];
        red[warp][8 + 2 * lr]     = accp[2];
        red[warp][8 + 2 * lr + 1] = accp[3];
    }
    __syncthreads();
    if (t < K1)
        ps[t] = (red[0][t] + red[1][t]) + (red[2][t] + red[3][t]);
    __syncthreads();

    // partial16 @ W23 -> 32-float contribution; fire-and-forget REDG into out[b].
    if (warp == 0) {
        float v = 0.f;
#pragma unroll
        for (int k = 0; k < K1; k++) v += ps[k] * W23s[k * NOUT + lane];
        redg_add(&out[(size_t)b * NOUT + lane], v);
    }
}

extern "C" void kernel_launch(void* const* d_in, const int* in_sizes, int n_in,
                              void* d_out, int out_size)
{
    const float* X  = (const float*)d_in[0];
    const int*   ss = (const int*)  d_in[1];
    const float* W1 = (const float*)d_in[2];
    const float* b1 = (const float*)d_in[3];
    const float* W2 = (const float*)d_in[4];
    const float* b2 = (const float*)d_in[5];
    const float* W3 = (const float*)d_in[6];
    const float* b3 = (const float*)d_in[7];
    float* o = (float*)d_out;
    setembed_init<<<(B_ * NOUT) / 256, 256>>>(ss, b2, W3, b3, o);
    setembed_main<<<B_ * NTILES, NTHREADS>>>(X, ss, W1, b1, W2, W3, o);
}

// round 17
// speedup vs baseline: 1.2495x; 1.0678x over previous
#include <cuda_runtime.h>
#include <cstdint>

// SetEmbed: out[b] = (sum_{s<n_b} relu(X[b,s]@W1 + b1)) @ W2 + n_b*b2, then @ W3 + b3.
// Linear-fold: out[b] = pooled16 @ (W2@W3) + n_b*(b2@W3) + b3.
//  K1 (init): writes constant term n_b*(b2@W3)+b3 into out, and computes
//             g_W23 = W2@W3 once (block 0).
//  K2 (main): one CTA per (batch, 128-row tile): cp.async staged X, 64x16 GEMM via
//      mma.sync.m16n8k8.tf32 (cvt.rna pre-round), row-masked relu+pool,
//      partial16 @ g_W23 (L2-hot), fire-and-forget red.global.add.f32 into out[b].

#define B_      2048
#define S_      512
#define NFT     64
#define K1      16
#define K2      12
#define NOUT    32
#define TSR     128
#define NTILES  (S_ / TSR)          // 4
#define RST     68                  // floats per smem row (pad: conflict-free frags)
#define NTHREADS 128

__device__ float g_W23[K1 * NOUT];  // W2@W3, computed by init each launch

__device__ __forceinline__ uint32_t f2tf32(float x) {
    uint32_t r;
    asm("cvt.rna.tf32.f32 %0, %1;" : "=r"(r) : "f"(x));
    return r;
}
__device__ __forceinline__ uint32_t smem_u32(const void* p) {
    return (uint32_t)__cvta_generic_to_shared(p);
}
__device__ __forceinline__ void mma16n8k8(float c[4], uint32_t a0, uint32_t a1,
                                          uint32_t a2, uint32_t a3,
                                          uint32_t b0, uint32_t b1) {
    asm volatile(
        "mma.sync.aligned.m16n8k8.row.col.f32.tf32.tf32.f32 "
        "{%0,%1,%2,%3}, {%4,%5,%6,%7}, {%8,%9}, {%0,%1,%2,%3};"
        : "+f"(c[0]), "+f"(c[1]), "+f"(c[2]), "+f"(c[3])
        : "r"(a0), "r"(a1), "r"(a2), "r"(a3), "r"(b0), "r"(b1));
}
__device__ __forceinline__ void redg_add(float* p, float v) {
    asm volatile("red.global.add.f32 [%0], %1;" :: "l"(p), "f"(v) : "memory");
}

// K1: out[b][o] = n_b*(b2@W3)[o] + b3[o];  block 0 also fills g_W23 = W2@W3.
__global__ __launch_bounds__(256) void setembed_init(
    const int* __restrict__ setSizes,
    const float* __restrict__ W2, const float* __restrict__ b2,
    const float* __restrict__ W3, const float* __restrict__ b3,
    float* __restrict__ out)
{
    __shared__ float c32[NOUT];
    const int t = threadIdx.x;
    if (blockIdx.x == 0) {           // g_W23[k][o], 512 entries, 2 per thread
#pragma unroll
        for (int e = 0; e < 2; e++) {
            int idx = t * 2 + e;
            int k = idx >> 5, o = idx & 31;
            float s = 0.f;
#pragma unroll
            for (int m = 0; m < K2; m++) s += W2[k * K2 + m] * W3[m * NOUT + o];
            g_W23[idx] = s;
        }
    }
    if (t < NOUT) {
        float s = 0.f;
#pragma unroll
        for (int m = 0; m < K2; m++) s += b2[m] * W3[m * NOUT + t];
        c32[t] = s;
    }
    __syncthreads();
    const int idx = blockIdx.x * 256 + t;   // 0 .. B_*NOUT-1
    const int b = idx >> 5, o = idx & 31;
    out[idx] = (float)setSizes[b] * c32[o] + b3[o];
}

__global__ __launch_bounds__(NTHREADS, 6) void setembed_main(
    const float* __restrict__ X, const int* __restrict__ setSizes,
    const float* __restrict__ W1, const float* __restrict__ b1,
    float* __restrict__ out)
{
    __shared__ __align__(16) float Xs[TSR * RST];    // 34816 B
    __shared__ float red[4][K1];
    __shared__ float ps[K1];

    const int bid  = blockIdx.x;
    const int b    = bid >> 2;
    const int tile = bid & 3;
    const int t    = threadIdx.x;
    const int n    = setSizes[b];
    const int base = tile * TSR;

    if (base >= n) return;            // inactive tile contributes exactly zero
    const int cnt = min(TSR, n - base);

    // Stage cnt rows, coalesced float4 cp.async. Tail rows stay garbage in smem;
    // their MMA outputs are masked before pooling (rows independent in the GEMM).
    {
        const float4* Xg = reinterpret_cast<const float4*>(
            X + (size_t)b * S_ * NFT) + (size_t)base * 16;
#pragma unroll
        for (int m = 0; m < 16; m++) {
            int idx = t + m * NTHREADS;       // 0..2047 float4 slots
            int r = idx >> 4, c = idx & 15;
            if (r < cnt) {
                unsigned da = smem_u32(&Xs[r * RST + c * 4]);
                asm volatile("cp.async.cg.shared.global [%0], [%1], 16;"
                             :: "r"(da), "l"(&Xg[r * 16 + c]));
            }
        }
        asm volatile("cp.async.commit_group;");
    }

    const int lane = t & 31, warp = t >> 5;
    const int lr = lane & 3;          // k-in-group / C col-pair id
    const int lg = lane >> 2;         // m-in-group / B n id

    // B fragments (W1^T as tf32), register-resident; overlaps cp.async.
    uint32_t bf[8][2][2];             // [kt][nt][b0/b1]
#pragma unroll
    for (int kt = 0; kt < 8; kt++)
#pragma unroll
        for (int nt = 0; nt < 2; nt++) {
            bf[kt][nt][0] = f2tf32(W1[(kt * 8 + lr)     * K1 + nt * 8 + lg]);
            bf[kt][nt][1] = f2tf32(W1[(kt * 8 + lr + 4) * K1 + nt * 8 + lg]);
        }
    float b1c[4];
    b1c[0] = b1[2 * lr];     b1c[1] = b1[2 * lr + 1];
    b1c[2] = b1[8 + 2 * lr]; b1c[3] = b1[8 + 2 * lr + 1];

    asm volatile("cp.async.wait_group 0;");
    __syncthreads();

    float accp[4] = {0.f, 0.f, 0.f, 0.f};
#pragma unroll
    for (int i = 0; i < 2; i++) {     // 2 m-tiles per warp
        const int r0b = (2 * warp + i) * 16;
        if (r0b < cnt) {              // warp-uniform guard
            float c0[4] = {0.f, 0.f, 0.f, 0.f};
            float c1[4] = {0.f, 0.f, 0.f, 0.f};
#pragma unroll
            for (int kt = 0; kt < 8; kt++) {
                const float* xp = &Xs[(r0b + lg) * RST + kt * 8 + lr];
                uint32_t a0 = f2tf32(xp[0]);
                uint32_t a1 = f2tf32(xp[8 * RST]);
                uint32_t a2 = f2tf32(xp[4]);
                uint32_t a3 = f2tf32(xp[8 * RST + 4]);
                mma16n8k8(c0, a0, a1, a2, a3, bf[kt][0][0], bf[kt][0][1]);
                mma16n8k8(c1, a0, a1, a2, a3, bf[kt][1][0], bf[kt][1][1]);
            }
            const int r0 = r0b + lg, r1 = r0 + 8;
            if (r0 < cnt) {           // relu + pool, row-masked
                accp[0] += fmaxf(c0[0] + b1c[0], 0.f);
                accp[1] += fmaxf(c0[1] + b1c[1], 0.f);
                accp[2] += fmaxf(c1[0] + b1c[2], 0.f);
                accp[3] += fmaxf(c1[1] + b1c[3], 0.f);
            }
            if (r1 < cnt) {
                accp[0] += fmaxf(c0[2] + b1c[0], 0.f);
                accp[1] += fmaxf(c0[3] + b1c[1], 0.f);
                accp[2] += fmaxf(c1[2] + b1c[2], 0.f);
                accp[3] += fmaxf(c1[3] + b1c[3], 0.f);
            }
        }
    }

    // Reduce over the 8 row-groups (lanes sharing lr). Deterministic per CTA.
#pragma unroll
    for (int j = 0; j < 4; j++) {
        accp[j] += __shfl_xor_sync(0xffffffffu, accp[j], 16);
        accp[j] += __shfl_xor_sync(0xffffffffu, accp[j], 8);
        accp[j] += __shfl_xor_sync(0xffffffffu, accp[j], 4);
    }
    if (lg == 0) {
        red[warp][2 * lr]         = accp[0];
        red[warp][2 * lr + 1]     = accp[1];
        red[warp][8 + 2 * lr]     = accp[2];
        red[warp][8 + 2 * lr + 1] = accp[3];
    }
    __syncthreads();
    if (t < K1)
        ps[t] = (red[0][t] + red[1][t]) + (red[2][t] + red[3][t]);
    __syncthreads();

    // partial16 @ g_W23 (L2-hot) -> 32-float contribution; fire-and-forget REDG.
    if (warp == 0) {
        float v = 0.f;
#pragma unroll
        for (int k = 0; k < K1; k++) v += ps[k] * g_W23[k * NOUT + lane];
        redg_add(&out[(size_t)b * NOUT + lane], v);
    }
}

extern "C" void kernel_launch(void* const* d_in, const int* in_sizes, int n_in,
                              void* d_out, int out_size)
{
    const float* X  = (const float*)d_in[0];
    const int*   ss = (const int*)  d_in[1];
    const float* W1 = (const float*)d_in[2];
    const float* b1 = (const float*)d_in[3];
    const float* W2 = (const float*)d_in[4];
    const float* b2 = (const float*)d_in[5];
    const float* W3 = (const float*)d_in[6];
    const float* b3 = (const float*)d_in[7];
    float* o = (float*)d_out;
    setembed_init<<<(B_ * NOUT) / 256, 256>>>(ss, W2, b2, W3, b3, o);
    setembed_main<<<B_ * NTILES, NTHREADS>>>(X, ss, W1, b1, o);
}